// round 15
// baseline (speedup 1.0000x reference)
#include <cuda_runtime.h>
#include <cuda_bf16.h>
#include <math.h>
#include <float.h>
#include <stdint.h>

#define BSZ   512
#define INDIM 4096
#define L1DIM 2048
#define DDIM  512
#define EDIM  64
#define KC    512
#define NROWS (BSZ*DDIM)
#define QDIM  (DDIM*EDIM)

#define OFF_VQ   0
#define OFF_XREC 1
#define OFF_PPL  (1 + BSZ*INDIM)
#define OFF_QST  (OFF_PPL + 1)
#define OFF_CLS  (OFF_QST + BSZ*QDIM)
#define OFF_ZENC (OFF_CLS + BSZ*10)

// ---------------- device scratch (R13 layout) ----------------
__device__ __align__(16) __nv_bfloat16 g_x3[(size_t)BSZ*3*INDIM];
__device__ __align__(16) __nv_bfloat16 g_We1t[(size_t)L1DIM*3*INDIM];
__device__ __align__(16) __nv_bfloat16 g_h3[(size_t)BSZ*3*L1DIM];
__device__ __align__(16) __nv_bfloat16 g_We2t[(size_t)DDIM*3*L1DIM];
__device__ __align__(16) float g_z0[BSZ*DDIM];
__device__ __align__(16) __nv_bfloat16 g_e3[(size_t)NROWS*3*EDIM];
__device__ __align__(16) __nv_bfloat16 g_Eb3[(size_t)KC*3*EDIM];
__device__ __align__(16) __nv_bfloat16 g_Ehi[(size_t)KC*EDIM];
__device__ __align__(16) __nv_bfloat16 g_Elo[(size_t)KC*EDIM];
__device__ __align__(16) float g_cdist[(size_t)NROWS*4];
__device__ __align__(16) int   g_cidx[(size_t)NROWS*4];
__device__ __align__(16) __nv_bfloat16 g_Wpt[(size_t)DDIM*3*QDIM];
__device__ __align__(16) int   g_idx[NROWS];
__device__ __align__(16) float g_counts[KC];
__device__ __align__(16) float g_part[1024];
__device__ __align__(16) float g_split[(size_t)8*BSZ*L1DIM];
__device__ __align__(16) float g_d1[BSZ*DDIM];
__device__ __align__(16) __nv_bfloat16 g_d2_3[(size_t)BSZ*3*DDIM];
__device__ __align__(16) __nv_bfloat16 g_Wd1t[(size_t)L1DIM*3*DDIM];
__device__ __align__(16) __nv_bfloat16 g_d3_3[(size_t)BSZ*3*L1DIM];
__device__ __align__(16) __nv_bfloat16 g_Wd2t[(size_t)INDIM*3*L1DIM];

// ---------------- PTX helpers ----------------
__device__ __forceinline__ uint32_t s2u(const void* p) {
    uint32_t a;
    asm("{ .reg .u64 t; cvta.to.shared.u64 t, %1; cvt.u32.u64 %0, t; }" : "=r"(a) : "l"(p));
    return a;
}
__device__ __forceinline__ uint32_t elect_one() {
    uint32_t pred;
    asm volatile("{\n\t.reg .pred p;\n\telect.sync _|p, 0xFFFFFFFF;\n\t"
                 "selp.b32 %0, 1, 0, p;\n\t}" : "=r"(pred));
    return pred;
}
#define SWZ(o) ((o) ^ (((o) >> 3) & 0x70))
static constexpr uint64_t DESC_BASE =
    (uint64_t(2) << 61) | (uint64_t(1) << 46) | (uint64_t(64) << 32) | (uint64_t(1) << 16);
#define MK_DESC(a) (DESC_BASE | ((uint64_t)((a) >> 4) & 0x3FFF))
#define IDESC_128 0x8200490u

__device__ __forceinline__ void mma_ss(uint32_t d, uint64_t a, uint64_t b, int acc) {
#ifdef __CUDA_ARCH_FEAT_SM103_ALL
    uint32_t z = 0;
    asm volatile(
        "{\n\t.reg .pred p;\n\tsetp.ne.u32 p, %5, 0;\n\t"
        "tcgen05.mma.cta_group::1.kind::f16 [%0], %1, %2, %3, {%4, %4, %4, %4}, p;\n\t}"
        :: "r"(d), "l"(a), "l"(b), "r"(IDESC_128), "r"(z), "r"((uint32_t)acc) : "memory");
#endif
}
__device__ __forceinline__ void tm_alloc(uint32_t sm, uint32_t n) {
#ifdef __CUDA_ARCH_FEAT_SM103_ALL
    asm volatile("tcgen05.alloc.cta_group::1.sync.aligned.shared::cta.b32 [%0], %1;"
                 :: "r"(sm), "r"(n) : "memory");
#endif
}
__device__ __forceinline__ void tm_dealloc(uint32_t t, uint32_t n) {
#ifdef __CUDA_ARCH_FEAT_SM103_ALL
    asm volatile("tcgen05.relinquish_alloc_permit.cta_group::1.sync.aligned;");
    asm volatile("tcgen05.dealloc.cta_group::1.sync.aligned.b32 %0, %1;" :: "r"(t), "r"(n));
#endif
}
__device__ __forceinline__ void tm_commit(uint32_t mb) {
#ifdef __CUDA_ARCH_FEAT_SM103_ALL
    asm volatile("tcgen05.commit.cta_group::1.mbarrier::arrive::one.shared::cluster.b64 [%0];"
                 :: "r"(mb) : "memory");
#endif
}
__device__ __forceinline__ void tm_fence_after() {
#ifdef __CUDA_ARCH_FEAT_SM103_ALL
    asm volatile("tcgen05.fence::after_thread_sync;" ::: "memory");
#endif
}
__device__ __forceinline__ void tm_fence_before() {
#ifdef __CUDA_ARCH_FEAT_SM103_ALL
    asm volatile("tcgen05.fence::before_thread_sync;" ::: "memory");
#endif
}
__device__ __forceinline__ void tm_wait_ld() {
#ifdef __CUDA_ARCH_FEAT_SM103_ALL
    asm volatile("tcgen05.wait::ld.sync.aligned;" ::: "memory");
#endif
}
__device__ __forceinline__ void ldtm32(uint32_t* r, uint32_t addr) {
#ifdef __CUDA_ARCH_FEAT_SM103_ALL
    asm volatile(
        "tcgen05.ld.sync.aligned.32x32b.x32.b32 "
        "{%0, %1, %2, %3, %4, %5, %6, %7, %8, %9, %10, %11, %12, %13, %14, %15, "
        " %16, %17, %18, %19, %20, %21, %22, %23, %24, %25, %26, %27, %28, %29, %30, %31}, [%32];"
        : "=r"(r[0]),  "=r"(r[1]),  "=r"(r[2]),  "=r"(r[3]),
          "=r"(r[4]),  "=r"(r[5]),  "=r"(r[6]),  "=r"(r[7]),
          "=r"(r[8]),  "=r"(r[9]),  "=r"(r[10]), "=r"(r[11]),
          "=r"(r[12]), "=r"(r[13]), "=r"(r[14]), "=r"(r[15]),
          "=r"(r[16]), "=r"(r[17]), "=r"(r[18]), "=r"(r[19]),
          "=r"(r[20]), "=r"(r[21]), "=r"(r[22]), "=r"(r[23]),
          "=r"(r[24]), "=r"(r[25]), "=r"(r[26]), "=r"(r[27]),
          "=r"(r[28]), "=r"(r[29]), "=r"(r[30]), "=r"(r[31])
        : "r"(addr));
#else
    for (int i = 0; i < 32; i++) r[i] = 0;
#endif
}
__device__ __forceinline__ void mbar_init(uint32_t a, uint32_t c) {
    asm volatile("mbarrier.init.shared.b64 [%0], %1;" :: "r"(a), "r"(c) : "memory");
}
__device__ __forceinline__ void mbar_wait(uint32_t addr, uint32_t parity) {
    uint32_t done;
    asm volatile("{\n\t.reg .pred p;\n\t"
                 "mbarrier.try_wait.parity.acquire.cta.shared::cta.b64 p, [%1], %2;\n\t"
                 "selp.b32 %0, 1, 0, p;\n\t}"
                 : "=r"(done) : "r"(addr), "r"(parity) : "memory");
    while (!done) {
        asm volatile("{\n\t.reg .pred p;\n\t"
                     "mbarrier.try_wait.parity.acquire.cta.shared::cta.b64 p, [%1], %2, 0x989680;\n\t"
                     "selp.b32 %0, 1, 0, p;\n\t}"
                     : "=r"(done) : "r"(addr), "r"(parity) : "memory");
    }
}
__device__ __forceinline__ void split2(float v, __nv_bfloat16& hi, __nv_bfloat16& lo) {
    hi = __float2bfloat16(v);
    lo = __float2bfloat16(v - __bfloat162float(hi));
}

// ============ tcgen05 split-K GEMM: partials (PROVEN R13 — FROZEN) ============
__global__ __launch_bounds__(256) void tc_gemm_partial(
    const __nv_bfloat16* __restrict__ A3, const __nv_bfloat16* __restrict__ B3,
    float* __restrict__ part, int N, long long K3, int kChunks)
{
    __shared__ __align__(1024) uint8_t sA[16384];
    __shared__ __align__(1024) uint8_t sB[16384];
    __shared__ uint32_t sTm[4];
    __shared__ __align__(8) unsigned long long sMbar;

    const int tid = threadIdx.x;
    const int wid = tid >> 5, lid = tid & 31;
    const int n0 = blockIdx.x * 128, m0 = blockIdx.y * 128;
    const int M = gridDim.y * 128;
    const long long kBeg = (long long)blockIdx.z * kChunks * 64;

    uint32_t ctrl = s2u(sTm), mbar = s2u(&sMbar);
    if (wid == 0) tm_alloc(ctrl, 128);
    if (tid == 0) mbar_init(mbar, 1);
    __syncthreads();
    uint32_t tmem;
    asm volatile("ld.shared.b32 %0, [%1];" : "=r"(tmem) : "r"(ctrl));

    uint64_t aDesc = MK_DESC(s2u(sA)), bDesc = MK_DESC(s2u(sB));

    for (int c = 0; c < kChunks; c++) {
        long long k0 = kBeg + (long long)c * 64;
#pragma unroll
        for (int it = 0; it < 4; it++) {
            int li = tid + it * 256;
            int row = li >> 3, seg = li & 7;
            uint32_t off = SWZ(row * 128 + seg * 16);
            *(float4*)(sA + off) = *(const float4*)(A3 + (size_t)(m0 + row) * K3 + k0 + seg * 8);
            *(float4*)(sB + off) = *(const float4*)(B3 + (size_t)(n0 + row) * K3 + k0 + seg * 8);
        }
        __syncthreads();
        if (wid == 0 && elect_one()) {
#pragma unroll
            for (int s = 0; s < 4; s++)
                mma_ss(tmem, aDesc + s * 2, bDesc + s * 2, (c > 0) || (s > 0));
            tm_commit(mbar);
        }
        mbar_wait(mbar, c & 1);
        __syncthreads();
    }
    tm_fence_after();

    if (wid < 4) {
        float* dst = part + (size_t)blockIdx.z * M * N;
        int m = m0 + wid * 32 + lid;
#pragma unroll
        for (int cg = 0; cg < 4; cg++) {
            uint32_t r[32];
            ldtm32(r, tmem + cg * 32);
            tm_wait_ld();
            float4* p = (float4*)(dst + (size_t)m * N + n0 + cg * 32);
#pragma unroll
            for (int j = 0; j < 8; j++)
                p[j] = make_float4(__uint_as_float(r[4*j]), __uint_as_float(r[4*j+1]),
                                   __uint_as_float(r[4*j+2]), __uint_as_float(r[4*j+3]));
        }
        tm_fence_before();
    }
    __syncthreads();
    if (wid == 0) tm_dealloc(tmem, 128);
}

// ============ gather-A variant for q@Wp (PROVEN R13 — FROZEN) ============
__global__ __launch_bounds__(256) void tc_gemm_gatherA(
    const int* __restrict__ idxArr, const __nv_bfloat16* __restrict__ Ehi,
    const __nv_bfloat16* __restrict__ Elo, const __nv_bfloat16* __restrict__ B3,
    float* __restrict__ part, int N, long long K3, int kChunks)
{
    __shared__ __align__(1024) uint8_t sA[16384];
    __shared__ __align__(1024) uint8_t sB[16384];
    __shared__ uint32_t sTm[4];
    __shared__ __align__(8) unsigned long long sMbar;

    const int tid = threadIdx.x;
    const int wid = tid >> 5, lid = tid & 31;
    const int n0 = blockIdx.x * 128, m0 = blockIdx.y * 128;
    const int M = gridDim.y * 128;
    const long long kBeg = (long long)blockIdx.z * kChunks * 64;

    uint32_t ctrl = s2u(sTm), mbar = s2u(&sMbar);
    if (wid == 0) tm_alloc(ctrl, 128);
    if (tid == 0) mbar_init(mbar, 1);
    __syncthreads();
    uint32_t tmem;
    asm volatile("ld.shared.b32 %0, [%1];" : "=r"(tmem) : "r"(ctrl));

    uint64_t aDesc = MK_DESC(s2u(sA)), bDesc = MK_DESC(s2u(sB));

    for (int c = 0; c < kChunks; c++) {
        long long k0 = kBeg + (long long)c * 64;
        int part_id = (int)(k0 >> 15);           // 0,1 -> hi ; 2 -> lo
        int d = (int)((k0 & 32767) >> 6);
        const __nv_bfloat16* tab = (part_id < 2) ? Ehi : Elo;
#pragma unroll
        for (int it = 0; it < 4; it++) {
            int li = tid + it * 256;
            int row = li >> 3, seg = li & 7;
            int code = idxArr[(size_t)(m0 + row) * 512 + d];
            uint32_t off = SWZ(row * 128 + seg * 16);
            *(float4*)(sA + off) = *(const float4*)(tab + (size_t)code * 64 + seg * 8);
            *(float4*)(sB + off) = *(const float4*)(B3 + (size_t)(n0 + row) * K3 + k0 + seg * 8);
        }
        __syncthreads();
        if (wid == 0 && elect_one()) {
#pragma unroll
            for (int s = 0; s < 4; s++)
                mma_ss(tmem, aDesc + s * 2, bDesc + s * 2, (c > 0) || (s > 0));
            tm_commit(mbar);
        }
        mbar_wait(mbar, c & 1);
        __syncthreads();
    }
    tm_fence_after();

    if (wid < 4) {
        float* dst = part + (size_t)blockIdx.z * M * N;
        int m = m0 + wid * 32 + lid;
#pragma unroll
        for (int cg = 0; cg < 4; cg++) {
            uint32_t r[32];
            ldtm32(r, tmem + cg * 32);
            tm_wait_ld();
            float4* p = (float4*)(dst + (size_t)m * N + n0 + cg * 32);
#pragma unroll
            for (int j = 0; j < 8; j++)
                p[j] = make_float4(__uint_as_float(r[4*j]), __uint_as_float(r[4*j+1]),
                                   __uint_as_float(r[4*j+2]), __uint_as_float(r[4*j+3]));
        }
        tm_fence_before();
    }
    __syncthreads();
    if (wid == 0) tm_dealloc(tmem, 128);
}

// ============ VQ dist: serial skeleton + candidate-argmin (PROVEN R13 — FROZEN) ====
__global__ __launch_bounds__(256) void tc_dist_cand(
    const __nv_bfloat16* __restrict__ e3, const __nv_bfloat16* __restrict__ Eb3,
    const float* __restrict__ E, float* __restrict__ cd, int* __restrict__ ci)
{
    __shared__ __align__(1024) uint8_t sA[16384];
    __shared__ __align__(1024) uint8_t sB[16384];
    __shared__ float ee[128];
    __shared__ uint32_t sTm[4];
    __shared__ __align__(8) unsigned long long sMbar;

    const int tid = threadIdx.x;
    const int wid = tid >> 5, lid = tid & 31;
    const int n0 = blockIdx.x * 128, m0 = blockIdx.y * 128;
    const long long K3 = 192;

    uint32_t ctrl = s2u(sTm), mbar = s2u(&sMbar);
    if (wid == 0) tm_alloc(ctrl, 128);
    if (tid == 0) mbar_init(mbar, 1);
    __syncthreads();
    uint32_t tmem;
    asm volatile("ld.shared.b32 %0, [%1];" : "=r"(tmem) : "r"(ctrl));

    if (tid < 128) {
        const float4* Er = (const float4*)(E + (size_t)(n0 + tid) * EDIM);
        float s = 0.f;
#pragma unroll
        for (int t = 0; t < 16; t++) {
            float4 v = Er[t];
            s += v.x * v.x + v.y * v.y + v.z * v.z + v.w * v.w;
        }
        ee[tid] = s;
    }

    uint64_t aDesc = MK_DESC(s2u(sA)), bDesc = MK_DESC(s2u(sB));

    for (int c = 0; c < 3; c++) {
        long long k0 = (long long)c * 64;
#pragma unroll
        for (int it = 0; it < 4; it++) {
            int li = tid + it * 256;
            int row = li >> 3, seg = li & 7;
            uint32_t off = SWZ(row * 128 + seg * 16);
            *(float4*)(sA + off) = *(const float4*)(e3 + (size_t)(m0 + row) * K3 + k0 + seg * 8);
            *(float4*)(sB + off) = *(const float4*)(Eb3 + (size_t)(n0 + row) * K3 + k0 + seg * 8);
        }
        __syncthreads();
        if (wid == 0 && elect_one()) {
#pragma unroll
            for (int s = 0; s < 4; s++)
                mma_ss(tmem, aDesc + s * 2, bDesc + s * 2, (c > 0) || (s > 0));
            tm_commit(mbar);
        }
        mbar_wait(mbar, c & 1);
        __syncthreads();
    }
    tm_fence_after();

    if (wid < 4) {
        int m = m0 + wid * 32 + lid;
        float best = FLT_MAX;
        int bi = 0;
#pragma unroll
        for (int cg = 0; cg < 4; cg++) {
            uint32_t r[32];
            ldtm32(r, tmem + cg * 32);
            tm_wait_ld();
#pragma unroll
            for (int j = 0; j < 32; j++) {
                int nl = cg * 32 + j;
                float dd = ee[nl] - 2.0f * __uint_as_float(r[j]);
                if (dd < best) { best = dd; bi = n0 + nl; }
            }
        }
        tm_fence_before();
        cd[(size_t)m * 4 + blockIdx.x] = best;
        ci[(size_t)m * 4 + blockIdx.x] = bi;
    }
    __syncthreads();
    if (wid == 0) tm_dealloc(tmem, 128);
}

// vq_reduce4 + counts zeroing (init_kernel merged)
__global__ void vq_reduce4(const float* __restrict__ cd, const int* __restrict__ ci,
                           int* __restrict__ idx, float* __restrict__ counts)
{
    int r = blockIdx.x * blockDim.x + threadIdx.x;
    if (r < KC) counts[r] = 0.f;
    if (r >= NROWS) return;
    float b = cd[(size_t)r * 4];
    int bi = ci[(size_t)r * 4];
#pragma unroll
    for (int t = 1; t < 4; t++) {
        float v = cd[(size_t)r * 4 + t];
        if (v < b) { b = v; bi = ci[(size_t)r * 4 + t]; }
    }
    idx[r] = bi;
}

// ============ elementwise / conversion kernels (R13) ============
__global__ void reduce_f32(const float* __restrict__ part, const float* __restrict__ bias,
                           float* __restrict__ out, int MN, int N, int splits)
{
    int i = blockIdx.x * blockDim.x + threadIdx.x;
    if (i >= MN) return;
    float s = bias[i % N];
    for (int z = 0; z < splits; z++) s += part[(size_t)z * MN + i];
    out[i] = fmaxf(s, 0.f);
}

__global__ void reduce_tri(const float* __restrict__ part, const float* __restrict__ bias,
                           __nv_bfloat16* __restrict__ out3, int MN, int N, int splits)
{
    int i = blockIdx.x * blockDim.x + threadIdx.x;
    if (i >= MN) return;
    int m = i / N, n = i % N;
    float s = bias[n];
    for (int z = 0; z < splits; z++) s += part[(size_t)z * MN + i];
    s = fmaxf(s, 0.f);
    __nv_bfloat16 hi, lo; split2(s, hi, lo);
    size_t base = (size_t)m * 3 * N + n;
    out3[base] = hi; out3[base + N] = hi; out3[base + 2 * N] = lo;
}

__global__ void conv_act(const float* __restrict__ X, __nv_bfloat16* __restrict__ X3,
                         int MK, int K)
{
    int i = blockIdx.x * blockDim.x + threadIdx.x;
    if (i >= MK) return;
    int m = i / K, k = i % K;
    __nv_bfloat16 hi, lo; split2(X[i], hi, lo);
    size_t base = (size_t)m * 3 * K + k;
    X3[base] = hi; X3[base + K] = hi; X3[base + 2 * K] = lo;
}

__global__ void conv_w(const float* __restrict__ W, __nv_bfloat16* __restrict__ B3,
                       int K, int N)
{
    __shared__ float t[32][33];
    int k0 = blockIdx.y * 32, n0 = blockIdx.x * 32;
#pragma unroll
    for (int r = 0; r < 4; r++) {
        int row = threadIdx.y + r * 8;
        t[row][threadIdx.x] = W[(size_t)(k0 + row) * N + n0 + threadIdx.x];
    }
    __syncthreads();
#pragma unroll
    for (int r = 0; r < 4; r++) {
        int nrow = threadIdx.y + r * 8;
        int k = threadIdx.x;
        __nv_bfloat16 hi, lo; split2(t[k][nrow], hi, lo);
        size_t base = (size_t)(n0 + nrow) * 3 * K + k0 + k;
        B3[base] = hi; B3[base + K] = lo; B3[base + 2 * K] = hi;
    }
}

__global__ void conv_E(const float* __restrict__ E, __nv_bfloat16* __restrict__ Eb3,
                       __nv_bfloat16* __restrict__ Ehi, __nv_bfloat16* __restrict__ Elo)
{
    int i = blockIdx.x * blockDim.x + threadIdx.x;
    if (i >= KC * EDIM) return;
    int n = i / EDIM, k = i % EDIM;
    __nv_bfloat16 hi, lo; split2(E[i], hi, lo);
    size_t base = (size_t)n * 3 * EDIM + k;
    Eb3[base] = hi; Eb3[base + EDIM] = lo; Eb3[base + 2 * EDIM] = hi;
    Ehi[(size_t)n * EDIM + k] = hi;
    Elo[(size_t)n * EDIM + k] = lo;
}

// ============ residual block (R13) ============
__global__ __launch_bounds__(256) void resblock_kernel(
    const float* __restrict__ X,
    const float* __restrict__ W1, const float* __restrict__ b1,
    const float* __restrict__ W2, const float* __restrict__ b2,
    const float* __restrict__ g,  const float* __restrict__ beta,
    float* __restrict__ out, __nv_bfloat16* __restrict__ out3)
{
    __shared__ float xr[DDIM];
    __shared__ float hp[16][17];
    __shared__ float hid[16];
    const int tid = threadIdx.x;
    const float* x = X + (size_t)blockIdx.x * DDIM;
    xr[tid] = x[tid];
    xr[tid + 256] = x[tid + 256];
    __syncthreads();

    int j = tid >> 4, s = tid & 15;
    float p = 0.f;
    int i0 = s * 32;
#pragma unroll 8
    for (int i = i0; i < i0 + 32; i++) p = fmaf(xr[i], W1[i * 16 + j], p);
    hp[j][s] = p;
    __syncthreads();
    if (tid < 16) {
        float v = b1[tid];
#pragma unroll
        for (int s2 = 0; s2 < 16; s2++) v += hp[tid][s2];
        hid[tid] = fmaxf(v, 0.f);
    }
    __syncthreads();

    const float inv = rsqrtf(1.0f + 1e-5f);
    for (int d = tid; d < DDIM; d += 256) {
        float u = b2[d];
#pragma unroll
        for (int j2 = 0; j2 < 16; j2++) u = fmaf(hid[j2], W2[j2 * DDIM + d], u);
        u = fmaxf(u, 0.f);
        float v = xr[d] + u * inv * g[d] + beta[d];
        if (out) out[(size_t)blockIdx.x * DDIM + d] = v;
        if (out3) {
            __nv_bfloat16 hi, lo; split2(v, hi, lo);
            size_t base = (size_t)blockIdx.x * 3 * DDIM + d;
            out3[base] = hi; out3[base + DDIM] = hi; out3[base + 2 * DDIM] = lo;
        }
    }
}

// ============ expansion MLP -> e3 triple (R13) ============
__global__ __launch_bounds__(256) void expand_kernel(
    const float* __restrict__ zenc,
    const float* __restrict__ Wt1, const float* __restrict__ bt1,
    const float* __restrict__ Wt2, const float* __restrict__ bt2,
    __nv_bfloat16* __restrict__ e3)
{
    __shared__ float w1[32], bb1[32], w2[32 * 64], bb2[64];
    const int tid = threadIdx.x;
    if (tid < 32) { w1[tid] = Wt1[tid]; bb1[tid] = bt1[tid]; }
    if (tid < 64) bb2[tid] = bt2[tid];
    for (int i = tid; i < 32 * 64; i += 256) w2[i] = Wt2[i];
    __syncthreads();

    int gid = blockIdx.x * 256 + tid;
    float z = zenc[gid];
    float h[32];
#pragma unroll
    for (int jj = 0; jj < 32; jj++) h[jj] = fmaxf(fmaf(z, w1[jj], bb1[jj]), 0.f);

    __nv_bfloat16* e3b = e3 + (size_t)gid * 3 * EDIM;
#pragma unroll
    for (int k = 0; k < 64; k += 4) {
        float4 a = make_float4(bb2[k], bb2[k + 1], bb2[k + 2], bb2[k + 3]);
#pragma unroll
        for (int jj = 0; jj < 32; jj++) {
            float hj = h[jj];
            a.x = fmaf(hj, w2[jj * 64 + k + 0], a.x);
            a.y = fmaf(hj, w2[jj * 64 + k + 1], a.y);
            a.z = fmaf(hj, w2[jj * 64 + k + 2], a.z);
            a.w = fmaf(hj, w2[jj * 64 + k + 3], a.w);
        }
        __nv_bfloat16 h0,l0,h1,l1,h2,l2,h3,l3;
        split2(a.x,h0,l0); split2(a.y,h1,l1); split2(a.z,h2,l2); split2(a.w,h3,l3);
        __nv_bfloat162 hp0 = {h0,h1}, hp1 = {h2,h3}, lp0 = {l0,l1}, lp1 = {l2,l3};
        *(__nv_bfloat162*)(e3b + k) = hp0;        *(__nv_bfloat162*)(e3b + k + 2) = hp1;
        *(__nv_bfloat162*)(e3b + 64 + k) = hp0;   *(__nv_bfloat162*)(e3b + 64 + k + 2) = hp1;
        *(__nv_bfloat162*)(e3b + 128 + k) = lp0;  *(__nv_bfloat162*)(e3b + 128 + k + 2) = lp1;
    }
}

// ============ gather: recompute e from zenc (bit-identical fmaf order, R13) ============
__global__ __launch_bounds__(256) void gather_kernel(
    const float* __restrict__ zenc,
    const float* __restrict__ Wt1, const float* __restrict__ bt1,
    const float* __restrict__ Wt2, const float* __restrict__ bt2,
    const float* __restrict__ E, const int* __restrict__ idx,
    float* __restrict__ q_out, float* __restrict__ counts, float* __restrict__ partial)
{
    __shared__ float w1[32], bb1[32], w2[32 * 64], bb2[64];
    __shared__ float red[256];
    const int tid = threadIdx.x;
    if (tid < 32) { w1[tid] = Wt1[tid]; bb1[tid] = bt1[tid]; }
    if (tid < 64) bb2[tid] = bt2[tid];
    for (int i = tid; i < 32 * 64; i += 256) w2[i] = Wt2[i];
    __syncthreads();

    int r = blockIdx.x * 256 + tid;
    int k = idx[r];
    atomicAdd(&counts[k], 1.0f);

    float z = zenc[r];
    float h[32];
#pragma unroll
    for (int jj = 0; jj < 32; jj++) h[jj] = fmaxf(fmaf(z, w1[jj], bb1[jj]), 0.f);

    const float4* Er = (const float4*)(E + (size_t)k * EDIM);
    float2* qo2 = (float2*)(q_out + (size_t)r * EDIM);

    float s = 0.f;
#pragma unroll
    for (int kk = 0; kk < 64; kk += 4) {
        float4 a = make_float4(bb2[kk], bb2[kk + 1], bb2[kk + 2], bb2[kk + 3]);
#pragma unroll
        for (int jj = 0; jj < 32; jj++) {
            float hj = h[jj];
            a.x = fmaf(hj, w2[jj * 64 + kk + 0], a.x);
            a.y = fmaf(hj, w2[jj * 64 + kk + 1], a.y);
            a.z = fmaf(hj, w2[jj * 64 + kk + 2], a.z);
            a.w = fmaf(hj, w2[jj * 64 + kk + 3], a.w);
        }
        float4 qv = Er[kk >> 2];
        qo2[(kk >> 1)]     = make_float2(qv.x, qv.y);
        qo2[(kk >> 1) + 1] = make_float2(qv.z, qv.w);
        float dx = qv.x - a.x, dy = qv.y - a.y, dz = qv.z - a.z, dw = qv.w - a.w;
        s += dx*dx + dy*dy + dz*dz + dw*dw;
    }

    red[tid] = s;
    __syncthreads();
    for (int off = 128; off > 0; off >>= 1) {
        if (tid < off) red[tid] += red[tid + off];
        __syncthreads();
    }
    if (tid == 0) partial[blockIdx.x] = red[0];
}

__global__ __launch_bounds__(512) void finalize_kernel(
    const float* __restrict__ partial, const float* __restrict__ counts,
    float* __restrict__ out)
{
    __shared__ float red[512];
    const int tid = threadIdx.x;
    red[tid] = partial[tid] + partial[tid + 512];
    __syncthreads();
    for (int off = 256; off > 0; off >>= 1) {
        if (tid < off) red[tid] += red[tid + off];
        __syncthreads();
    }
    if (tid == 0) out[OFF_VQ] = 1.25f * red[0] / (float)((size_t)NROWS * EDIM);
    __syncthreads();

    float p = counts[tid] * (1.0f / (float)NROWS);
    red[tid] = p * logf(p + 1e-10f);
    __syncthreads();
    for (int off = 256; off > 0; off >>= 1) {
        if (tid < off) red[tid] += red[tid + off];
        __syncthreads();
    }
    if (tid == 0) out[OFF_PPL] = expf(-red[0]);
}

__global__ __launch_bounds__(256) void cls_kernel(
    const float* __restrict__ q, const float* __restrict__ Wc,
    const float* __restrict__ bc, float* __restrict__ out)
{
    const int tid = threadIdx.x;
    const int b = blockIdx.x;
    const float* qr = q + (size_t)b * QDIM;
    float acc[10];
#pragma unroll
    for (int c = 0; c < 10; c++) acc[c] = 0.f;
    for (int i = tid; i < QDIM; i += 256) {
        float qv = qr[i];
        const float* w = Wc + (size_t)i * 10;
#pragma unroll
        for (int c = 0; c < 10; c++) acc[c] = fmaf(qv, w[c], acc[c]);
    }
    __shared__ float red[256];
#pragma unroll
    for (int c = 0; c < 10; c++) {
        red[tid] = acc[c];
        __syncthreads();
        for (int off = 128; off > 0; off >>= 1) {
            if (tid < off) red[tid] += red[tid + off];
            __syncthreads();
        }
        if (tid == 0) {
            float v = red[0] + bc[c];
            out[(size_t)b * 10 + c] = 1.0f / (1.0f + expf(-v));
        }
        __syncthreads();
    }
}

// =====================================================================
static void* symaddr(const void* sym) {
    void* p = nullptr;
    cudaGetSymbolAddress(&p, sym);
    return p;
}

extern "C" void kernel_launch(void* const* d_in, const int* in_sizes, int n_in,
                              void* d_out, int out_size)
{
    const float* x    = (const float*)d_in[0];
    const float* We1  = (const float*)d_in[1];
    const float* be1  = (const float*)d_in[2];
    const float* We2  = (const float*)d_in[3];
    const float* be2  = (const float*)d_in[4];
    const float* Wre1 = (const float*)d_in[5];
    const float* bre1 = (const float*)d_in[6];
    const float* Wre2 = (const float*)d_in[7];
    const float* bre2 = (const float*)d_in[8];
    const float* ge   = (const float*)d_in[9];
    const float* bebn = (const float*)d_in[10];
    const float* E    = (const float*)d_in[11];
    const float* Wt1  = (const float*)d_in[12];
    const float* bt1  = (const float*)d_in[13];
    const float* Wt2  = (const float*)d_in[14];
    const float* bt2  = (const float*)d_in[15];
    const float* Wc   = (const float*)d_in[16];
    const float* bc   = (const float*)d_in[17];
    const float* Wp   = (const float*)d_in[18];
    const float* bp   = (const float*)d_in[19];
    const float* Wrd1 = (const float*)d_in[20];
    const float* brd1 = (const float*)d_in[21];
    const float* Wrd2 = (const float*)d_in[22];
    const float* brd2 = (const float*)d_in[23];
    const float* gd   = (const float*)d_in[24];
    const float* bdbn = (const float*)d_in[25];
    const float* Wd1  = (const float*)d_in[26];
    const float* bd1  = (const float*)d_in[27];
    const float* Wd2  = (const float*)d_in[28];
    const float* bd2  = (const float*)d_in[29];

    float* out = (float*)d_out;

    __nv_bfloat16* px3   = (__nv_bfloat16*)symaddr(g_x3);
    __nv_bfloat16* pWe1t = (__nv_bfloat16*)symaddr(g_We1t);
    __nv_bfloat16* ph3   = (__nv_bfloat16*)symaddr(g_h3);
    __nv_bfloat16* pWe2t = (__nv_bfloat16*)symaddr(g_We2t);
    float* pz0           = (float*)symaddr(g_z0);
    __nv_bfloat16* pe3   = (__nv_bfloat16*)symaddr(g_e3);
    __nv_bfloat16* pEb3  = (__nv_bfloat16*)symaddr(g_Eb3);
    __nv_bfloat16* pEhi  = (__nv_bfloat16*)symaddr(g_Ehi);
    __nv_bfloat16* pElo  = (__nv_bfloat16*)symaddr(g_Elo);
    float* pcd           = (float*)symaddr(g_cdist);
    int*   pci           = (int*)symaddr(g_cidx);
    __nv_bfloat16* pWpt  = (__nv_bfloat16*)symaddr(g_Wpt);
    int*   pidx          = (int*)symaddr(g_idx);
    float* pcnt          = (float*)symaddr(g_counts);
    float* ppart         = (float*)symaddr(g_part);
    float* psplit        = (float*)symaddr(g_split);
    float* pd1           = (float*)symaddr(g_d1);
    __nv_bfloat16* pd2_3 = (__nv_bfloat16*)symaddr(g_d2_3);
    __nv_bfloat16* pWd1t = (__nv_bfloat16*)symaddr(g_Wd1t);
    __nv_bfloat16* pd3_3 = (__nv_bfloat16*)symaddr(g_d3_3);
    __nv_bfloat16* pWd2t = (__nv_bfloat16*)symaddr(g_Wd2t);

    // ---- conversions ----
    conv_act<<<(BSZ * INDIM + 255) / 256, 256>>>(x, px3, BSZ * INDIM, INDIM);
    conv_w<<<dim3(L1DIM / 32, INDIM / 32), dim3(32, 8)>>>(We1, pWe1t, INDIM, L1DIM);
    conv_w<<<dim3(DDIM / 32, L1DIM / 32), dim3(32, 8)>>>(We2, pWe2t, L1DIM, DDIM);
    conv_w<<<dim3(DDIM / 32, QDIM / 32), dim3(32, 8)>>>(Wp, pWpt, QDIM, DDIM);
    conv_w<<<dim3(L1DIM / 32, DDIM / 32), dim3(32, 8)>>>(Wd1, pWd1t, DDIM, L1DIM);
    conv_w<<<dim3(INDIM / 32, L1DIM / 32), dim3(32, 8)>>>(Wd2, pWd2t, L1DIM, INDIM);
    conv_E<<<(KC * EDIM + 255) / 256, 256>>>(E, pEb3, pEhi, pElo);

    // ---- encoder GEMM1: h = relu(x@We1+be1), 8 splits (512 CTAs) ----
    tc_gemm_partial<<<dim3(L1DIM/128, BSZ/128, 8), 256>>>(px3, pWe1t, psplit,
                                                          L1DIM, 3LL*INDIM, 24);
    reduce_tri<<<(BSZ*L1DIM+255)/256, 256>>>(psplit, be1, ph3, BSZ*L1DIM, L1DIM, 8);

    // ---- encoder GEMM2: z0 = relu(h@We2+be2), 32 splits (512 CTAs, was 256) ----
    tc_gemm_partial<<<dim3(DDIM/128, BSZ/128, 32), 256>>>(ph3, pWe2t, psplit,
                                                          DDIM, 3LL*L1DIM, 3);
    reduce_f32<<<(BSZ*DDIM+255)/256, 256>>>(psplit, be2, pz0, BSZ*DDIM, DDIM, 32);

    // ---- encoder resblock -> zenc ----
    resblock_kernel<<<BSZ, 256>>>(pz0, Wre1, bre1, Wre2, bre2, ge, bebn,
                                  out + OFF_ZENC, nullptr);

    // ---- VQ ----
    expand_kernel<<<NROWS/256, 256>>>(out + OFF_ZENC, Wt1, bt1, Wt2, bt2, pe3);
    tc_dist_cand<<<dim3(KC/128, NROWS/128, 1), 256>>>(pe3, pEb3, E, pcd, pci);
    vq_reduce4<<<(NROWS + 255)/256, 256>>>(pcd, pci, pidx, pcnt);
    gather_kernel<<<NROWS/256, 256>>>(out + OFF_ZENC, Wt1, bt1, Wt2, bt2,
                                      E, pidx, out + OFF_QST, pcnt, ppart);
    finalize_kernel<<<1, 512>>>(ppart, pcnt, out);
    cls_kernel<<<BSZ, 256>>>(out + OFF_QST, Wc, bc, out + OFF_CLS);

    // ---- decoder GEMM Wp: 32 splits (512 CTAs) ----
    tc_gemm_gatherA<<<dim3(DDIM/128, BSZ/128, 32), 256>>>(pidx, pEhi, pElo, pWpt,
                                                          psplit, DDIM, 3LL*QDIM, 48);
    reduce_f32<<<(BSZ*DDIM+255)/256, 256>>>(psplit, bp, pd1, BSZ*DDIM, DDIM, 32);

    // ---- decoder resblock ----
    resblock_kernel<<<BSZ, 256>>>(pd1, Wrd1, brd1, Wrd2, brd2, gd, bdbn,
                                  nullptr, pd2_3);

    // ---- decoder GEMM Wd1: 8 splits (512 CTAs, was 256) ----
    tc_gemm_partial<<<dim3(L1DIM/128, BSZ/128, 8), 256>>>(pd2_3, pWd1t, psplit,
                                                          L1DIM, 3LL*DDIM, 3);
    reduce_tri<<<(BSZ*L1DIM+255)/256, 256>>>(psplit, bd1, pd3_3, BSZ*L1DIM, L1DIM, 8);

    // ---- decoder GEMM Wd2: 4 splits (512 CTAs) ----
    tc_gemm_partial<<<dim3(INDIM/128, BSZ/128, 4), 256>>>(pd3_3, pWd2t, psplit,
                                                          INDIM, 3LL*L1DIM, 24);
    reduce_f32<<<(BSZ*INDIM+255)/256, 256>>>(psplit, bd2, out + OFF_XREC,
                                             BSZ*INDIM, INDIM, 4);
}

// round 16
// speedup vs baseline: 1.0158x; 1.0158x over previous
#include <cuda_runtime.h>
#include <cuda_bf16.h>
#include <math.h>
#include <float.h>
#include <stdint.h>

#define BSZ   512
#define INDIM 4096
#define L1DIM 2048
#define DDIM  512
#define EDIM  64
#define KC    512
#define NROWS (BSZ*DDIM)
#define QDIM  (DDIM*EDIM)

#define OFF_VQ   0
#define OFF_XREC 1
#define OFF_PPL  (1 + BSZ*INDIM)
#define OFF_QST  (OFF_PPL + 1)
#define OFF_CLS  (OFF_QST + BSZ*QDIM)
#define OFF_ZENC (OFF_CLS + BSZ*10)

// ---------------- device scratch (R13 layout) ----------------
__device__ __align__(16) __nv_bfloat16 g_x3[(size_t)BSZ*3*INDIM];
__device__ __align__(16) __nv_bfloat16 g_We1t[(size_t)L1DIM*3*INDIM];
__device__ __align__(16) __nv_bfloat16 g_h3[(size_t)BSZ*3*L1DIM];
__device__ __align__(16) __nv_bfloat16 g_We2t[(size_t)DDIM*3*L1DIM];
__device__ __align__(16) float g_z0[BSZ*DDIM];
__device__ __align__(16) __nv_bfloat16 g_e3[(size_t)NROWS*3*EDIM];
__device__ __align__(16) __nv_bfloat16 g_Eb3[(size_t)KC*3*EDIM];
__device__ __align__(16) __nv_bfloat16 g_Ehi[(size_t)KC*EDIM];
__device__ __align__(16) __nv_bfloat16 g_Elo[(size_t)KC*EDIM];
__device__ __align__(16) float g_cdist[(size_t)NROWS*4];
__device__ __align__(16) int   g_cidx[(size_t)NROWS*4];
__device__ __align__(16) __nv_bfloat16 g_Wpt[(size_t)DDIM*3*QDIM];
__device__ __align__(16) int   g_idx[NROWS];
__device__ __align__(16) float g_counts[KC];
__device__ __align__(16) float g_part[1024];
__device__ __align__(16) float g_split[(size_t)8*BSZ*L1DIM];
__device__ __align__(16) float g_d1[BSZ*DDIM];
__device__ __align__(16) __nv_bfloat16 g_d2_3[(size_t)BSZ*3*DDIM];
__device__ __align__(16) __nv_bfloat16 g_Wd1t[(size_t)L1DIM*3*DDIM];
__device__ __align__(16) __nv_bfloat16 g_d3_3[(size_t)BSZ*3*L1DIM];
__device__ __align__(16) __nv_bfloat16 g_Wd2t[(size_t)INDIM*3*L1DIM];

// ---------------- PTX helpers ----------------
__device__ __forceinline__ uint32_t s2u(const void* p) {
    uint32_t a;
    asm("{ .reg .u64 t; cvta.to.shared.u64 t, %1; cvt.u32.u64 %0, t; }" : "=r"(a) : "l"(p));
    return a;
}
__device__ __forceinline__ uint32_t elect_one() {
    uint32_t pred;
    asm volatile("{\n\t.reg .pred p;\n\telect.sync _|p, 0xFFFFFFFF;\n\t"
                 "selp.b32 %0, 1, 0, p;\n\t}" : "=r"(pred));
    return pred;
}
#define SWZ(o) ((o) ^ (((o) >> 3) & 0x70))
static constexpr uint64_t DESC_BASE =
    (uint64_t(2) << 61) | (uint64_t(1) << 46) | (uint64_t(64) << 32) | (uint64_t(1) << 16);
#define MK_DESC(a) (DESC_BASE | ((uint64_t)((a) >> 4) & 0x3FFF))
#define IDESC_128 0x8200490u

__device__ __forceinline__ void mma_ss(uint32_t d, uint64_t a, uint64_t b, int acc) {
#ifdef __CUDA_ARCH_FEAT_SM103_ALL
    uint32_t z = 0;
    asm volatile(
        "{\n\t.reg .pred p;\n\tsetp.ne.u32 p, %5, 0;\n\t"
        "tcgen05.mma.cta_group::1.kind::f16 [%0], %1, %2, %3, {%4, %4, %4, %4}, p;\n\t}"
        :: "r"(d), "l"(a), "l"(b), "r"(IDESC_128), "r"(z), "r"((uint32_t)acc) : "memory");
#endif
}
__device__ __forceinline__ void tm_alloc(uint32_t sm, uint32_t n) {
#ifdef __CUDA_ARCH_FEAT_SM103_ALL
    asm volatile("tcgen05.alloc.cta_group::1.sync.aligned.shared::cta.b32 [%0], %1;"
                 :: "r"(sm), "r"(n) : "memory");
#endif
}
__device__ __forceinline__ void tm_dealloc(uint32_t t, uint32_t n) {
#ifdef __CUDA_ARCH_FEAT_SM103_ALL
    asm volatile("tcgen05.relinquish_alloc_permit.cta_group::1.sync.aligned;");
    asm volatile("tcgen05.dealloc.cta_group::1.sync.aligned.b32 %0, %1;" :: "r"(t), "r"(n));
#endif
}
__device__ __forceinline__ void tm_commit(uint32_t mb) {
#ifdef __CUDA_ARCH_FEAT_SM103_ALL
    asm volatile("tcgen05.commit.cta_group::1.mbarrier::arrive::one.shared::cluster.b64 [%0];"
                 :: "r"(mb) : "memory");
#endif
}
__device__ __forceinline__ void tm_fence_after() {
#ifdef __CUDA_ARCH_FEAT_SM103_ALL
    asm volatile("tcgen05.fence::after_thread_sync;" ::: "memory");
#endif
}
__device__ __forceinline__ void tm_fence_before() {
#ifdef __CUDA_ARCH_FEAT_SM103_ALL
    asm volatile("tcgen05.fence::before_thread_sync;" ::: "memory");
#endif
}
__device__ __forceinline__ void tm_wait_ld() {
#ifdef __CUDA_ARCH_FEAT_SM103_ALL
    asm volatile("tcgen05.wait::ld.sync.aligned;" ::: "memory");
#endif
}
__device__ __forceinline__ void ldtm32(uint32_t* r, uint32_t addr) {
#ifdef __CUDA_ARCH_FEAT_SM103_ALL
    asm volatile(
        "tcgen05.ld.sync.aligned.32x32b.x32.b32 "
        "{%0, %1, %2, %3, %4, %5, %6, %7, %8, %9, %10, %11, %12, %13, %14, %15, "
        " %16, %17, %18, %19, %20, %21, %22, %23, %24, %25, %26, %27, %28, %29, %30, %31}, [%32];"
        : "=r"(r[0]),  "=r"(r[1]),  "=r"(r[2]),  "=r"(r[3]),
          "=r"(r[4]),  "=r"(r[5]),  "=r"(r[6]),  "=r"(r[7]),
          "=r"(r[8]),  "=r"(r[9]),  "=r"(r[10]), "=r"(r[11]),
          "=r"(r[12]), "=r"(r[13]), "=r"(r[14]), "=r"(r[15]),
          "=r"(r[16]), "=r"(r[17]), "=r"(r[18]), "=r"(r[19]),
          "=r"(r[20]), "=r"(r[21]), "=r"(r[22]), "=r"(r[23]),
          "=r"(r[24]), "=r"(r[25]), "=r"(r[26]), "=r"(r[27]),
          "=r"(r[28]), "=r"(r[29]), "=r"(r[30]), "=r"(r[31])
        : "r"(addr));
#else
    for (int i = 0; i < 32; i++) r[i] = 0;
#endif
}
__device__ __forceinline__ void mbar_init(uint32_t a, uint32_t c) {
    asm volatile("mbarrier.init.shared.b64 [%0], %1;" :: "r"(a), "r"(c) : "memory");
}
__device__ __forceinline__ void mbar_wait(uint32_t addr, uint32_t parity) {
    uint32_t done;
    asm volatile("{\n\t.reg .pred p;\n\t"
                 "mbarrier.try_wait.parity.acquire.cta.shared::cta.b64 p, [%1], %2;\n\t"
                 "selp.b32 %0, 1, 0, p;\n\t}"
                 : "=r"(done) : "r"(addr), "r"(parity) : "memory");
    while (!done) {
        asm volatile("{\n\t.reg .pred p;\n\t"
                     "mbarrier.try_wait.parity.acquire.cta.shared::cta.b64 p, [%1], %2, 0x989680;\n\t"
                     "selp.b32 %0, 1, 0, p;\n\t}"
                     : "=r"(done) : "r"(addr), "r"(parity) : "memory");
    }
}
__device__ __forceinline__ void split2(float v, __nv_bfloat16& hi, __nv_bfloat16& lo) {
    hi = __float2bfloat16(v);
    lo = __float2bfloat16(v - __bfloat162float(hi));
}

// ============ tcgen05 split-K GEMM: partials (PROVEN R13 — FROZEN) ============
__global__ __launch_bounds__(256) void tc_gemm_partial(
    const __nv_bfloat16* __restrict__ A3, const __nv_bfloat16* __restrict__ B3,
    float* __restrict__ part, int N, long long K3, int kChunks)
{
    __shared__ __align__(1024) uint8_t sA[16384];
    __shared__ __align__(1024) uint8_t sB[16384];
    __shared__ uint32_t sTm[4];
    __shared__ __align__(8) unsigned long long sMbar;

    const int tid = threadIdx.x;
    const int wid = tid >> 5, lid = tid & 31;
    const int n0 = blockIdx.x * 128, m0 = blockIdx.y * 128;
    const int M = gridDim.y * 128;
    const long long kBeg = (long long)blockIdx.z * kChunks * 64;

    uint32_t ctrl = s2u(sTm), mbar = s2u(&sMbar);
    if (wid == 0) tm_alloc(ctrl, 128);
    if (tid == 0) mbar_init(mbar, 1);
    __syncthreads();
    uint32_t tmem;
    asm volatile("ld.shared.b32 %0, [%1];" : "=r"(tmem) : "r"(ctrl));

    uint64_t aDesc = MK_DESC(s2u(sA)), bDesc = MK_DESC(s2u(sB));

    for (int c = 0; c < kChunks; c++) {
        long long k0 = kBeg + (long long)c * 64;
#pragma unroll
        for (int it = 0; it < 4; it++) {
            int li = tid + it * 256;
            int row = li >> 3, seg = li & 7;
            uint32_t off = SWZ(row * 128 + seg * 16);
            *(float4*)(sA + off) = *(const float4*)(A3 + (size_t)(m0 + row) * K3 + k0 + seg * 8);
            *(float4*)(sB + off) = *(const float4*)(B3 + (size_t)(n0 + row) * K3 + k0 + seg * 8);
        }
        __syncthreads();
        if (wid == 0 && elect_one()) {
#pragma unroll
            for (int s = 0; s < 4; s++)
                mma_ss(tmem, aDesc + s * 2, bDesc + s * 2, (c > 0) || (s > 0));
            tm_commit(mbar);
        }
        mbar_wait(mbar, c & 1);
        __syncthreads();
    }
    tm_fence_after();

    if (wid < 4) {
        float* dst = part + (size_t)blockIdx.z * M * N;
        int m = m0 + wid * 32 + lid;
#pragma unroll
        for (int cg = 0; cg < 4; cg++) {
            uint32_t r[32];
            ldtm32(r, tmem + cg * 32);
            tm_wait_ld();
            float4* p = (float4*)(dst + (size_t)m * N + n0 + cg * 32);
#pragma unroll
            for (int j = 0; j < 8; j++)
                p[j] = make_float4(__uint_as_float(r[4*j]), __uint_as_float(r[4*j+1]),
                                   __uint_as_float(r[4*j+2]), __uint_as_float(r[4*j+3]));
        }
        tm_fence_before();
    }
    __syncthreads();
    if (wid == 0) tm_dealloc(tmem, 128);
}

// ============ gather-A variant for q@Wp (PROVEN R13 — FROZEN) ============
__global__ __launch_bounds__(256) void tc_gemm_gatherA(
    const int* __restrict__ idxArr, const __nv_bfloat16* __restrict__ Ehi,
    const __nv_bfloat16* __restrict__ Elo, const __nv_bfloat16* __restrict__ B3,
    float* __restrict__ part, int N, long long K3, int kChunks)
{
    __shared__ __align__(1024) uint8_t sA[16384];
    __shared__ __align__(1024) uint8_t sB[16384];
    __shared__ uint32_t sTm[4];
    __shared__ __align__(8) unsigned long long sMbar;

    const int tid = threadIdx.x;
    const int wid = tid >> 5, lid = tid & 31;
    const int n0 = blockIdx.x * 128, m0 = blockIdx.y * 128;
    const int M = gridDim.y * 128;
    const long long kBeg = (long long)blockIdx.z * kChunks * 64;

    uint32_t ctrl = s2u(sTm), mbar = s2u(&sMbar);
    if (wid == 0) tm_alloc(ctrl, 128);
    if (tid == 0) mbar_init(mbar, 1);
    __syncthreads();
    uint32_t tmem;
    asm volatile("ld.shared.b32 %0, [%1];" : "=r"(tmem) : "r"(ctrl));

    uint64_t aDesc = MK_DESC(s2u(sA)), bDesc = MK_DESC(s2u(sB));

    for (int c = 0; c < kChunks; c++) {
        long long k0 = kBeg + (long long)c * 64;
        int part_id = (int)(k0 >> 15);           // 0,1 -> hi ; 2 -> lo
        int d = (int)((k0 & 32767) >> 6);
        const __nv_bfloat16* tab = (part_id < 2) ? Ehi : Elo;
#pragma unroll
        for (int it = 0; it < 4; it++) {
            int li = tid + it * 256;
            int row = li >> 3, seg = li & 7;
            int code = idxArr[(size_t)(m0 + row) * 512 + d];
            uint32_t off = SWZ(row * 128 + seg * 16);
            *(float4*)(sA + off) = *(const float4*)(tab + (size_t)code * 64 + seg * 8);
            *(float4*)(sB + off) = *(const float4*)(B3 + (size_t)(n0 + row) * K3 + k0 + seg * 8);
        }
        __syncthreads();
        if (wid == 0 && elect_one()) {
#pragma unroll
            for (int s = 0; s < 4; s++)
                mma_ss(tmem, aDesc + s * 2, bDesc + s * 2, (c > 0) || (s > 0));
            tm_commit(mbar);
        }
        mbar_wait(mbar, c & 1);
        __syncthreads();
    }
    tm_fence_after();

    if (wid < 4) {
        float* dst = part + (size_t)blockIdx.z * M * N;
        int m = m0 + wid * 32 + lid;
#pragma unroll
        for (int cg = 0; cg < 4; cg++) {
            uint32_t r[32];
            ldtm32(r, tmem + cg * 32);
            tm_wait_ld();
            float4* p = (float4*)(dst + (size_t)m * N + n0 + cg * 32);
#pragma unroll
            for (int j = 0; j < 8; j++)
                p[j] = make_float4(__uint_as_float(r[4*j]), __uint_as_float(r[4*j+1]),
                                   __uint_as_float(r[4*j+2]), __uint_as_float(r[4*j+3]));
        }
        tm_fence_before();
    }
    __syncthreads();
    if (wid == 0) tm_dealloc(tmem, 128);
}

// ============ VQ dist: serial skeleton + candidate-argmin (PROVEN R13 — FROZEN) ====
__global__ __launch_bounds__(256) void tc_dist_cand(
    const __nv_bfloat16* __restrict__ e3, const __nv_bfloat16* __restrict__ Eb3,
    const float* __restrict__ E, float* __restrict__ cd, int* __restrict__ ci)
{
    __shared__ __align__(1024) uint8_t sA[16384];
    __shared__ __align__(1024) uint8_t sB[16384];
    __shared__ float ee[128];
    __shared__ uint32_t sTm[4];
    __shared__ __align__(8) unsigned long long sMbar;

    const int tid = threadIdx.x;
    const int wid = tid >> 5, lid = tid & 31;
    const int n0 = blockIdx.x * 128, m0 = blockIdx.y * 128;
    const long long K3 = 192;

    uint32_t ctrl = s2u(sTm), mbar = s2u(&sMbar);
    if (wid == 0) tm_alloc(ctrl, 128);
    if (tid == 0) mbar_init(mbar, 1);
    __syncthreads();
    uint32_t tmem;
    asm volatile("ld.shared.b32 %0, [%1];" : "=r"(tmem) : "r"(ctrl));

    if (tid < 128) {
        const float4* Er = (const float4*)(E + (size_t)(n0 + tid) * EDIM);
        float s = 0.f;
#pragma unroll
        for (int t = 0; t < 16; t++) {
            float4 v = Er[t];
            s += v.x * v.x + v.y * v.y + v.z * v.z + v.w * v.w;
        }
        ee[tid] = s;
    }

    uint64_t aDesc = MK_DESC(s2u(sA)), bDesc = MK_DESC(s2u(sB));

    for (int c = 0; c < 3; c++) {
        long long k0 = (long long)c * 64;
#pragma unroll
        for (int it = 0; it < 4; it++) {
            int li = tid + it * 256;
            int row = li >> 3, seg = li & 7;
            uint32_t off = SWZ(row * 128 + seg * 16);
            *(float4*)(sA + off) = *(const float4*)(e3 + (size_t)(m0 + row) * K3 + k0 + seg * 8);
            *(float4*)(sB + off) = *(const float4*)(Eb3 + (size_t)(n0 + row) * K3 + k0 + seg * 8);
        }
        __syncthreads();
        if (wid == 0 && elect_one()) {
#pragma unroll
            for (int s = 0; s < 4; s++)
                mma_ss(tmem, aDesc + s * 2, bDesc + s * 2, (c > 0) || (s > 0));
            tm_commit(mbar);
        }
        mbar_wait(mbar, c & 1);
        __syncthreads();
    }
    tm_fence_after();

    if (wid < 4) {
        int m = m0 + wid * 32 + lid;
        float best = FLT_MAX;
        int bi = 0;
#pragma unroll
        for (int cg = 0; cg < 4; cg++) {
            uint32_t r[32];
            ldtm32(r, tmem + cg * 32);
            tm_wait_ld();
#pragma unroll
            for (int j = 0; j < 32; j++) {
                int nl = cg * 32 + j;
                float dd = ee[nl] - 2.0f * __uint_as_float(r[j]);
                if (dd < best) { best = dd; bi = n0 + nl; }
            }
        }
        tm_fence_before();
        cd[(size_t)m * 4 + blockIdx.x] = best;
        ci[(size_t)m * 4 + blockIdx.x] = bi;
    }
    __syncthreads();
    if (wid == 0) tm_dealloc(tmem, 128);
}

// vq_reduce4 + counts zeroing (merged, proven R15)
__global__ void vq_reduce4(const float* __restrict__ cd, const int* __restrict__ ci,
                           int* __restrict__ idx, float* __restrict__ counts)
{
    int r = blockIdx.x * blockDim.x + threadIdx.x;
    if (r < KC) counts[r] = 0.f;
    if (r >= NROWS) return;
    float b = cd[(size_t)r * 4];
    int bi = ci[(size_t)r * 4];
#pragma unroll
    for (int t = 1; t < 4; t++) {
        float v = cd[(size_t)r * 4 + t];
        if (v < b) { b = v; bi = ci[(size_t)r * 4 + t]; }
    }
    idx[r] = bi;
}

// ============ elementwise / conversion kernels (R13) ============
__global__ void reduce_f32(const float* __restrict__ part, const float* __restrict__ bias,
                           float* __restrict__ out, int MN, int N, int splits)
{
    int i = blockIdx.x * blockDim.x + threadIdx.x;
    if (i >= MN) return;
    float s = bias[i % N];
    for (int z = 0; z < splits; z++) s += part[(size_t)z * MN + i];
    out[i] = fmaxf(s, 0.f);
}

__global__ void reduce_tri(const float* __restrict__ part, const float* __restrict__ bias,
                           __nv_bfloat16* __restrict__ out3, int MN, int N, int splits)
{
    int i = blockIdx.x * blockDim.x + threadIdx.x;
    if (i >= MN) return;
    int m = i / N, n = i % N;
    float s = bias[n];
    for (int z = 0; z < splits; z++) s += part[(size_t)z * MN + i];
    s = fmaxf(s, 0.f);
    __nv_bfloat16 hi, lo; split2(s, hi, lo);
    size_t base = (size_t)m * 3 * N + n;
    out3[base] = hi; out3[base + N] = hi; out3[base + 2 * N] = lo;
}

__global__ void conv_act(const float* __restrict__ X, __nv_bfloat16* __restrict__ X3,
                         int MK, int K)
{
    int i = blockIdx.x * blockDim.x + threadIdx.x;
    if (i >= MK) return;
    int m = i / K, k = i % K;
    __nv_bfloat16 hi, lo; split2(X[i], hi, lo);
    size_t base = (size_t)m * 3 * K + k;
    X3[base] = hi; X3[base + K] = hi; X3[base + 2 * K] = lo;
}

__global__ void conv_w(const float* __restrict__ W, __nv_bfloat16* __restrict__ B3,
                       int K, int N)
{
    __shared__ float t[32][33];
    int k0 = blockIdx.y * 32, n0 = blockIdx.x * 32;
#pragma unroll
    for (int r = 0; r < 4; r++) {
        int row = threadIdx.y + r * 8;
        t[row][threadIdx.x] = W[(size_t)(k0 + row) * N + n0 + threadIdx.x];
    }
    __syncthreads();
#pragma unroll
    for (int r = 0; r < 4; r++) {
        int nrow = threadIdx.y + r * 8;
        int k = threadIdx.x;
        __nv_bfloat16 hi, lo; split2(t[k][nrow], hi, lo);
        size_t base = (size_t)(n0 + nrow) * 3 * K + k0 + k;
        B3[base] = hi; B3[base + K] = lo; B3[base + 2 * K] = hi;
    }
}

__global__ void conv_E(const float* __restrict__ E, __nv_bfloat16* __restrict__ Eb3,
                       __nv_bfloat16* __restrict__ Ehi, __nv_bfloat16* __restrict__ Elo)
{
    int i = blockIdx.x * blockDim.x + threadIdx.x;
    if (i >= KC * EDIM) return;
    int n = i / EDIM, k = i % EDIM;
    __nv_bfloat16 hi, lo; split2(E[i], hi, lo);
    size_t base = (size_t)n * 3 * EDIM + k;
    Eb3[base] = hi; Eb3[base + EDIM] = lo; Eb3[base + 2 * EDIM] = hi;
    Ehi[(size_t)n * EDIM + k] = hi;
    Elo[(size_t)n * EDIM + k] = lo;
}

// ============ residual block (R13) ============
__global__ __launch_bounds__(256) void resblock_kernel(
    const float* __restrict__ X,
    const float* __restrict__ W1, const float* __restrict__ b1,
    const float* __restrict__ W2, const float* __restrict__ b2,
    const float* __restrict__ g,  const float* __restrict__ beta,
    float* __restrict__ out, __nv_bfloat16* __restrict__ out3)
{
    __shared__ float xr[DDIM];
    __shared__ float hp[16][17];
    __shared__ float hid[16];
    const int tid = threadIdx.x;
    const float* x = X + (size_t)blockIdx.x * DDIM;
    xr[tid] = x[tid];
    xr[tid + 256] = x[tid + 256];
    __syncthreads();

    int j = tid >> 4, s = tid & 15;
    float p = 0.f;
    int i0 = s * 32;
#pragma unroll 8
    for (int i = i0; i < i0 + 32; i++) p = fmaf(xr[i], W1[i * 16 + j], p);
    hp[j][s] = p;
    __syncthreads();
    if (tid < 16) {
        float v = b1[tid];
#pragma unroll
        for (int s2 = 0; s2 < 16; s2++) v += hp[tid][s2];
        hid[tid] = fmaxf(v, 0.f);
    }
    __syncthreads();

    const float inv = rsqrtf(1.0f + 1e-5f);
    for (int d = tid; d < DDIM; d += 256) {
        float u = b2[d];
#pragma unroll
        for (int j2 = 0; j2 < 16; j2++) u = fmaf(hid[j2], W2[j2 * DDIM + d], u);
        u = fmaxf(u, 0.f);
        float v = xr[d] + u * inv * g[d] + beta[d];
        if (out) out[(size_t)blockIdx.x * DDIM + d] = v;
        if (out3) {
            __nv_bfloat16 hi, lo; split2(v, hi, lo);
            size_t base = (size_t)blockIdx.x * 3 * DDIM + d;
            out3[base] = hi; out3[base + DDIM] = hi; out3[base + 2 * DDIM] = lo;
        }
    }
}

// ============ expansion MLP -> e3 triple (R13) ============
__global__ __launch_bounds__(256) void expand_kernel(
    const float* __restrict__ zenc,
    const float* __restrict__ Wt1, const float* __restrict__ bt1,
    const float* __restrict__ Wt2, const float* __restrict__ bt2,
    __nv_bfloat16* __restrict__ e3)
{
    __shared__ float w1[32], bb1[32], w2[32 * 64], bb2[64];
    const int tid = threadIdx.x;
    if (tid < 32) { w1[tid] = Wt1[tid]; bb1[tid] = bt1[tid]; }
    if (tid < 64) bb2[tid] = bt2[tid];
    for (int i = tid; i < 32 * 64; i += 256) w2[i] = Wt2[i];
    __syncthreads();

    int gid = blockIdx.x * 256 + tid;
    float z = zenc[gid];
    float h[32];
#pragma unroll
    for (int jj = 0; jj < 32; jj++) h[jj] = fmaxf(fmaf(z, w1[jj], bb1[jj]), 0.f);

    __nv_bfloat16* e3b = e3 + (size_t)gid * 3 * EDIM;
#pragma unroll
    for (int k = 0; k < 64; k += 4) {
        float4 a = make_float4(bb2[k], bb2[k + 1], bb2[k + 2], bb2[k + 3]);
#pragma unroll
        for (int jj = 0; jj < 32; jj++) {
            float hj = h[jj];
            a.x = fmaf(hj, w2[jj * 64 + k + 0], a.x);
            a.y = fmaf(hj, w2[jj * 64 + k + 1], a.y);
            a.z = fmaf(hj, w2[jj * 64 + k + 2], a.z);
            a.w = fmaf(hj, w2[jj * 64 + k + 3], a.w);
        }
        __nv_bfloat16 h0,l0,h1,l1,h2,l2,h3,l3;
        split2(a.x,h0,l0); split2(a.y,h1,l1); split2(a.z,h2,l2); split2(a.w,h3,l3);
        __nv_bfloat162 hp0 = {h0,h1}, hp1 = {h2,h3}, lp0 = {l0,l1}, lp1 = {l2,l3};
        *(__nv_bfloat162*)(e3b + k) = hp0;        *(__nv_bfloat162*)(e3b + k + 2) = hp1;
        *(__nv_bfloat162*)(e3b + 64 + k) = hp0;   *(__nv_bfloat162*)(e3b + 64 + k + 2) = hp1;
        *(__nv_bfloat162*)(e3b + 128 + k) = lp0;  *(__nv_bfloat162*)(e3b + 128 + k + 2) = lp1;
    }
}

// ============ gather: recompute e from zenc (bit-identical fmaf order, R13) ============
__global__ __launch_bounds__(256) void gather_kernel(
    const float* __restrict__ zenc,
    const float* __restrict__ Wt1, const float* __restrict__ bt1,
    const float* __restrict__ Wt2, const float* __restrict__ bt2,
    const float* __restrict__ E, const int* __restrict__ idx,
    float* __restrict__ q_out, float* __restrict__ counts, float* __restrict__ partial)
{
    __shared__ float w1[32], bb1[32], w2[32 * 64], bb2[64];
    __shared__ float red[256];
    const int tid = threadIdx.x;
    if (tid < 32) { w1[tid] = Wt1[tid]; bb1[tid] = bt1[tid]; }
    if (tid < 64) bb2[tid] = bt2[tid];
    for (int i = tid; i < 32 * 64; i += 256) w2[i] = Wt2[i];
    __syncthreads();

    int r = blockIdx.x * 256 + tid;
    int k = idx[r];
    atomicAdd(&counts[k], 1.0f);

    float z = zenc[r];
    float h[32];
#pragma unroll
    for (int jj = 0; jj < 32; jj++) h[jj] = fmaxf(fmaf(z, w1[jj], bb1[jj]), 0.f);

    const float4* Er = (const float4*)(E + (size_t)k * EDIM);
    float2* qo2 = (float2*)(q_out + (size_t)r * EDIM);

    float s = 0.f;
#pragma unroll
    for (int kk = 0; kk < 64; kk += 4) {
        float4 a = make_float4(bb2[kk], bb2[kk + 1], bb2[kk + 2], bb2[kk + 3]);
#pragma unroll
        for (int jj = 0; jj < 32; jj++) {
            float hj = h[jj];
            a.x = fmaf(hj, w2[jj * 64 + kk + 0], a.x);
            a.y = fmaf(hj, w2[jj * 64 + kk + 1], a.y);
            a.z = fmaf(hj, w2[jj * 64 + kk + 2], a.z);
            a.w = fmaf(hj, w2[jj * 64 + kk + 3], a.w);
        }
        float4 qv = Er[kk >> 2];
        qo2[(kk >> 1)]     = make_float2(qv.x, qv.y);
        qo2[(kk >> 1) + 1] = make_float2(qv.z, qv.w);
        float dx = qv.x - a.x, dy = qv.y - a.y, dz = qv.z - a.z, dw = qv.w - a.w;
        s += dx*dx + dy*dy + dz*dz + dw*dw;
    }

    red[tid] = s;
    __syncthreads();
    for (int off = 128; off > 0; off >>= 1) {
        if (tid < off) red[tid] += red[tid + off];
        __syncthreads();
    }
    if (tid == 0) partial[blockIdx.x] = red[0];
}

__global__ __launch_bounds__(512) void finalize_kernel(
    const float* __restrict__ partial, const float* __restrict__ counts,
    float* __restrict__ out)
{
    __shared__ float red[512];
    const int tid = threadIdx.x;
    red[tid] = partial[tid] + partial[tid + 512];
    __syncthreads();
    for (int off = 256; off > 0; off >>= 1) {
        if (tid < off) red[tid] += red[tid + off];
        __syncthreads();
    }
    if (tid == 0) out[OFF_VQ] = 1.25f * red[0] / (float)((size_t)NROWS * EDIM);
    __syncthreads();

    float p = counts[tid] * (1.0f / (float)NROWS);
    red[tid] = p * logf(p + 1e-10f);
    __syncthreads();
    for (int off = 256; off > 0; off >>= 1) {
        if (tid < off) red[tid] += red[tid + off];
        __syncthreads();
    }
    if (tid == 0) out[OFF_PPL] = expf(-red[0]);
}

__global__ __launch_bounds__(256) void cls_kernel(
    const float* __restrict__ q, const float* __restrict__ Wc,
    const float* __restrict__ bc, float* __restrict__ out)
{
    const int tid = threadIdx.x;
    const int b = blockIdx.x;
    const float* qr = q + (size_t)b * QDIM;
    float acc[10];
#pragma unroll
    for (int c = 0; c < 10; c++) acc[c] = 0.f;
    for (int i = tid; i < QDIM; i += 256) {
        float qv = qr[i];
        const float* w = Wc + (size_t)i * 10;
#pragma unroll
        for (int c = 0; c < 10; c++) acc[c] = fmaf(qv, w[c], acc[c]);
    }
    __shared__ float red[256];
#pragma unroll
    for (int c = 0; c < 10; c++) {
        red[tid] = acc[c];
        __syncthreads();
        for (int off = 128; off > 0; off >>= 1) {
            if (tid < off) red[tid] += red[tid + off];
            __syncthreads();
        }
        if (tid == 0) {
            float v = red[0] + bc[c];
            out[(size_t)b * 10 + c] = 1.0f / (1.0f + expf(-v));
        }
        __syncthreads();
    }
}

// =====================================================================
static void* symaddr(const void* sym) {
    void* p = nullptr;
    cudaGetSymbolAddress(&p, sym);
    return p;
}

extern "C" void kernel_launch(void* const* d_in, const int* in_sizes, int n_in,
                              void* d_out, int out_size)
{
    const float* x    = (const float*)d_in[0];
    const float* We1  = (const float*)d_in[1];
    const float* be1  = (const float*)d_in[2];
    const float* We2  = (const float*)d_in[3];
    const float* be2  = (const float*)d_in[4];
    const float* Wre1 = (const float*)d_in[5];
    const float* bre1 = (const float*)d_in[6];
    const float* Wre2 = (const float*)d_in[7];
    const float* bre2 = (const float*)d_in[8];
    const float* ge   = (const float*)d_in[9];
    const float* bebn = (const float*)d_in[10];
    const float* E    = (const float*)d_in[11];
    const float* Wt1  = (const float*)d_in[12];
    const float* bt1  = (const float*)d_in[13];
    const float* Wt2  = (const float*)d_in[14];
    const float* bt2  = (const float*)d_in[15];
    const float* Wc   = (const float*)d_in[16];
    const float* bc   = (const float*)d_in[17];
    const float* Wp   = (const float*)d_in[18];
    const float* bp   = (const float*)d_in[19];
    const float* Wrd1 = (const float*)d_in[20];
    const float* brd1 = (const float*)d_in[21];
    const float* Wrd2 = (const float*)d_in[22];
    const float* brd2 = (const float*)d_in[23];
    const float* gd   = (const float*)d_in[24];
    const float* bdbn = (const float*)d_in[25];
    const float* Wd1  = (const float*)d_in[26];
    const float* bd1  = (const float*)d_in[27];
    const float* Wd2  = (const float*)d_in[28];
    const float* bd2  = (const float*)d_in[29];

    float* out = (float*)d_out;

    __nv_bfloat16* px3   = (__nv_bfloat16*)symaddr(g_x3);
    __nv_bfloat16* pWe1t = (__nv_bfloat16*)symaddr(g_We1t);
    __nv_bfloat16* ph3   = (__nv_bfloat16*)symaddr(g_h3);
    __nv_bfloat16* pWe2t = (__nv_bfloat16*)symaddr(g_We2t);
    float* pz0           = (float*)symaddr(g_z0);
    __nv_bfloat16* pe3   = (__nv_bfloat16*)symaddr(g_e3);
    __nv_bfloat16* pEb3  = (__nv_bfloat16*)symaddr(g_Eb3);
    __nv_bfloat16* pEhi  = (__nv_bfloat16*)symaddr(g_Ehi);
    __nv_bfloat16* pElo  = (__nv_bfloat16*)symaddr(g_Elo);
    float* pcd           = (float*)symaddr(g_cdist);
    int*   pci           = (int*)symaddr(g_cidx);
    __nv_bfloat16* pWpt  = (__nv_bfloat16*)symaddr(g_Wpt);
    int*   pidx          = (int*)symaddr(g_idx);
    float* pcnt          = (float*)symaddr(g_counts);
    float* ppart         = (float*)symaddr(g_part);
    float* psplit        = (float*)symaddr(g_split);
    float* pd1           = (float*)symaddr(g_d1);
    __nv_bfloat16* pd2_3 = (__nv_bfloat16*)symaddr(g_d2_3);
    __nv_bfloat16* pWd1t = (__nv_bfloat16*)symaddr(g_Wd1t);
    __nv_bfloat16* pd3_3 = (__nv_bfloat16*)symaddr(g_d3_3);
    __nv_bfloat16* pWd2t = (__nv_bfloat16*)symaddr(g_Wd2t);

    // ---- launch order arranged so tc_gemm_partial (GEMM1) lands in the
    //      ncu capture slot (4th launch); dependencies preserved ----
    conv_act<<<(BSZ * INDIM + 255) / 256, 256>>>(x, px3, BSZ * INDIM, INDIM);        // 1
    conv_E<<<(KC * EDIM + 255) / 256, 256>>>(E, pEb3, pEhi, pElo);                   // 2
    conv_w<<<dim3(L1DIM / 32, INDIM / 32), dim3(32, 8)>>>(We1, pWe1t, INDIM, L1DIM); // 3

    // ---- encoder GEMM1: h = relu(x@We1+be1), 8 splits ----                        // 4
    tc_gemm_partial<<<dim3(L1DIM/128, BSZ/128, 8), 256>>>(px3, pWe1t, psplit,
                                                          L1DIM, 3LL*INDIM, 24);
    reduce_tri<<<(BSZ*L1DIM+255)/256, 256>>>(psplit, be1, ph3, BSZ*L1DIM, L1DIM, 8); // 5

    conv_w<<<dim3(DDIM / 32, L1DIM / 32), dim3(32, 8)>>>(We2, pWe2t, L1DIM, DDIM);   // 6

    // ---- encoder GEMM2: z0 = relu(h@We2+be2), 16 splits (R13 proven) ----
    tc_gemm_partial<<<dim3(DDIM/128, BSZ/128, 16), 256>>>(ph3, pWe2t, psplit,
                                                          DDIM, 3LL*L1DIM, 6);
    reduce_f32<<<(BSZ*DDIM+255)/256, 256>>>(psplit, be2, pz0, BSZ*DDIM, DDIM, 16);

    // ---- encoder resblock -> zenc ----
    resblock_kernel<<<BSZ, 256>>>(pz0, Wre1, bre1, Wre2, bre2, ge, bebn,
                                  out + OFF_ZENC, nullptr);

    // ---- VQ ----
    expand_kernel<<<NROWS/256, 256>>>(out + OFF_ZENC, Wt1, bt1, Wt2, bt2, pe3);
    tc_dist_cand<<<dim3(KC/128, NROWS/128, 1), 256>>>(pe3, pEb3, E, pcd, pci);
    vq_reduce4<<<(NROWS + 255)/256, 256>>>(pcd, pci, pidx, pcnt);
    gather_kernel<<<NROWS/256, 256>>>(out + OFF_ZENC, Wt1, bt1, Wt2, bt2,
                                      E, pidx, out + OFF_QST, pcnt, ppart);
    finalize_kernel<<<1, 512>>>(ppart, pcnt, out);
    cls_kernel<<<BSZ, 256>>>(out + OFF_QST, Wc, bc, out + OFF_CLS);

    // ---- decoder GEMM Wp: 32 splits (R13 proven) ----
    conv_w<<<dim3(DDIM / 32, QDIM / 32), dim3(32, 8)>>>(Wp, pWpt, QDIM, DDIM);
    tc_gemm_gatherA<<<dim3(DDIM/128, BSZ/128, 32), 256>>>(pidx, pEhi, pElo, pWpt,
                                                          psplit, DDIM, 3LL*QDIM, 48);
    reduce_f32<<<(BSZ*DDIM+255)/256, 256>>>(psplit, bp, pd1, BSZ*DDIM, DDIM, 32);

    // ---- decoder resblock ----
    resblock_kernel<<<BSZ, 256>>>(pd1, Wrd1, brd1, Wrd2, brd2, gd, bdbn,
                                  nullptr, pd2_3);

    // ---- decoder GEMM Wd1: 4 splits (R13 proven) ----
    conv_w<<<dim3(L1DIM / 32, DDIM / 32), dim3(32, 8)>>>(Wd1, pWd1t, DDIM, L1DIM);
    tc_gemm_partial<<<dim3(L1DIM/128, BSZ/128, 4), 256>>>(pd2_3, pWd1t, psplit,
                                                          L1DIM, 3LL*DDIM, 6);
    reduce_tri<<<(BSZ*L1DIM+255)/256, 256>>>(psplit, bd1, pd3_3, BSZ*L1DIM, L1DIM, 4);

    // ---- decoder GEMM Wd2: 4 splits (R13 proven) ----
    conv_w<<<dim3(INDIM / 32, L1DIM / 32), dim3(32, 8)>>>(Wd2, pWd2t, L1DIM, INDIM);
    tc_gemm_partial<<<dim3(INDIM/128, BSZ/128, 4), 256>>>(pd3_3, pWd2t, psplit,
                                                          INDIM, 3LL*L1DIM, 24);
    reduce_f32<<<(BSZ*INDIM+255)/256, 256>>>(psplit, bd2, out + OFF_XREC,
                                             BSZ*INDIM, INDIM, 4);
}